// round 5
// baseline (speedup 1.0000x reference)
#include <cuda_runtime.h>

// Persistent neural-CDE kernel. 128 CTAs (one per batch row AND one per
// hidden-unit slice), 512 threads. W1/W2/dup-W3 resident in smem. Cross-CTA
// exchange via __device__ buffers; contention-free flag-array grid barrier
// (padded arrival slots + per-CTA padded go flags).

#define NCTAS 128
#define NT    512

typedef unsigned long long u64;

__device__ float g_h2T[128 * 128];     // [k][r]
__device__ float g_dz [128 * 128];     // [b][h]
__device__ float g_dx [128 * 3 * 32];  // [b][sel][c]
__device__ unsigned int g_slot[128 * 8];  // arrival counters, 32B stride
__device__ unsigned int g_go  [128 * 8];  // per-CTA release flags, 32B stride

__device__ __forceinline__ void grid_barrier(unsigned int target)
{
    __syncthreads();
    if (blockIdx.x == 0) {
        if (threadIdx.x < 32) {
            const int lane = threadIdx.x;
            if (lane == 0) {
                __threadfence();
                asm volatile("st.release.gpu.b32 [%0], %1;"
                             :: "l"(g_slot), "r"(target) : "memory");
            }
            const unsigned int* p0 = g_slot + (lane * 4 + 0) * 8;
            const unsigned int* p1 = g_slot + (lane * 4 + 1) * 8;
            const unsigned int* p2 = g_slot + (lane * 4 + 2) * 8;
            const unsigned int* p3 = g_slot + (lane * 4 + 3) * 8;
            bool ok;
            do {
                unsigned int a, b, c, d;
                asm volatile("ld.relaxed.gpu.b32 %0, [%1];" : "=r"(a) : "l"(p0) : "memory");
                asm volatile("ld.relaxed.gpu.b32 %0, [%1];" : "=r"(b) : "l"(p1) : "memory");
                asm volatile("ld.relaxed.gpu.b32 %0, [%1];" : "=r"(c) : "l"(p2) : "memory");
                asm volatile("ld.relaxed.gpu.b32 %0, [%1];" : "=r"(d) : "l"(p3) : "memory");
                ok = (a == target) && (b == target) && (c == target) && (d == target);
            } while (!__all_sync(0xffffffffu, ok));
            asm volatile("fence.acq_rel.gpu;" ::: "memory");
            #pragma unroll
            for (int i = 0; i < 4; i++)
                asm volatile("st.relaxed.gpu.b32 [%0], %1;"
                             :: "l"(g_go + (lane * 4 + i) * 8), "r"(target) : "memory");
        }
    } else {
        if (threadIdx.x == 0) {
            __threadfence();
            asm volatile("st.release.gpu.b32 [%0], %1;"
                         :: "l"(g_slot + blockIdx.x * 8), "r"(target) : "memory");
            unsigned int g;
            do {
                asm volatile("ld.acquire.gpu.b32 %0, [%1];"
                             : "=r"(g) : "l"(g_go + blockIdx.x * 8) : "memory");
            } while (g != target);
        }
    }
    __syncthreads();
}

// GEMV: out[j] = relu(b[j] + sum_k v[k]*W[k][j]); operands in smem.
// 512 threads: 32 j-quads x 16 k-chunks of 8.
__device__ __forceinline__ void gemv128(const float* __restrict__ vs,
                                        const float* __restrict__ Wsm,
                                        const float* __restrict__ bsm,
                                        float* __restrict__ outv,
                                        float* __restrict__ sp)
{
    const int tid = threadIdx.x;
    const int j0 = (tid & 31) << 2, k0 = (tid >> 5) << 3;
    float4 vv0 = *(const float4*)(vs + k0);
    float4 vv1 = *(const float4*)(vs + k0 + 4);
    float4 acc = make_float4(0.f, 0.f, 0.f, 0.f);
    const float* wb = Wsm + k0 * 128 + j0;
    #define GSTEP(VK, KK) { float4 w4 = *(const float4*)(wb + (KK) * 128); \
        acc.x = fmaf(VK, w4.x, acc.x); acc.y = fmaf(VK, w4.y, acc.y);     \
        acc.z = fmaf(VK, w4.z, acc.z); acc.w = fmaf(VK, w4.w, acc.w); }
    GSTEP(vv0.x, 0) GSTEP(vv0.y, 1) GSTEP(vv0.z, 2) GSTEP(vv0.w, 3)
    GSTEP(vv1.x, 4) GSTEP(vv1.y, 5) GSTEP(vv1.z, 6) GSTEP(vv1.w, 7)
    #undef GSTEP
    *(float4*)(sp + (tid >> 5) * 128 + j0) = acc;
    __syncthreads();
    if (tid < 128) {
        float s = bsm[tid];
        #pragma unroll
        for (int q = 0; q < 16; q++)
            s += sp[q * 128 + tid];
        outv[tid] = fmaxf(s, 0.0f);
    }
    __syncthreads();
}

// cephes-style rational tanh: returns p, writes q; tanh(x) = p/q. FMA-only.
__device__ __forceinline__ float tanh_pq(float x, float& qo)
{
    x = fminf(fmaxf(x, -7.90531110591164f), 7.90531110591164f);
    float x2 = x * x;
    float p = fmaf(x2, -2.76076847742355e-16f, 2.00018790482477e-13f);
    p = fmaf(p, x2, -8.60467152213735e-11f);
    p = fmaf(p, x2,  5.12229709037114e-08f);
    p = fmaf(p, x2,  1.48572235717979e-05f);
    p = fmaf(p, x2,  6.37261928875436e-04f);
    p = fmaf(p, x2,  4.89352455891786e-03f);
    p = p * x;
    float q = fmaf(x2, 1.19825839466702e-06f, 1.18534705686654e-04f);
    q = fmaf(q, x2, 2.26843463243900e-03f);
    qo = fmaf(q, x2, 4.89352518554385e-03f);
    return p;
}

__device__ __forceinline__ void rcp4(const float* q, float* inv)
{
    float a01 = q[0] * q[1], a23 = q[2] * q[3], P = a01 * a23, R;
    asm("rcp.approx.f32 %0, %1;" : "=f"(R) : "f"(P));
    inv[0] = R * q[1] * a23;
    inv[1] = R * q[0] * a23;
    inv[2] = R * a01 * q[3];
    inv[3] = R * a01 * q[2];
}

// smem (floats): h2s 16384 | w1s 16384 | w2s 16384 | w3d 8192 |
//                b1s 128 | b2s 128 | ys 128 | zs 128 | kacc 128 | misc 16
// sp (2048) / h1s (128) / h2row (128) alias the dead front of h2s.
#define SMEM_FLOATS (16384*3 + 8192 + 5*128 + 16)
#define SMEM_BYTES  (SMEM_FLOATS * 4)

extern __shared__ float smem[];

__global__ __launch_bounds__(NT, 1)
void cde_kernel(const float* __restrict__ coeffs,
                const float* __restrict__ W1, const float* __restrict__ b1,
                const float* __restrict__ W2, const float* __restrict__ b2,
                const float* __restrict__ W3, const float* __restrict__ b3,
                const float* __restrict__ Wi, const float* __restrict__ bi,
                const float* __restrict__ Wr, const float* __restrict__ br,
                float* __restrict__ out)
{
    float* h2s   = smem;                // [k][b] 128x128
    float* w1s   = h2s  + 16384;        // [k][j]
    float* w2s   = w1s  + 16384;
    float* w3d   = w2s  + 16384;        // [k][2c dup] 128x64
    float* b1s   = w3d  + 8192;
    float* b2s   = b1s  + 128;
    float* ys    = b2s  + 128;
    float* zs    = ys   + 128;
    float* kacc  = zs   + 128;
    unsigned int* sbase = (unsigned int*)(kacc + 128);
    float* sp    = h2s;                 // aliases (dead before h2s copy)
    float* h1s   = h2s + 2048;
    float* h2row = h2s + 2176;

    const int tid = threadIdx.x;
    const int r   = blockIdx.x;         // owned batch row == owned h-slice

    if (tid == 0) {
        unsigned int g0;
        asm volatile("ld.relaxed.gpu.b32 %0, [%1];"
                     : "=r"(g0) : "l"(g_slot + blockIdx.x * 8));
        *sbase = g0;
    }

    // ---- prologue: stage weights ----
    #pragma unroll
    for (int i = 0; i < 8; i++) {
        int idx = tid + i * NT;
        ((float4*)w1s)[idx] = ((const float4*)W1)[idx];
        ((float4*)w2s)[idx] = ((const float4*)W2)[idx];
    }
    #pragma unroll
    for (int i = 0; i < 8; i++) {       // dup-W3 slice: [k][2c],[k][2c+1]
        int idx = tid + i * NT;
        int k = idx >> 5, c = idx & 31;
        float w = W3[k * 4096 + r * 32 + c];
        *(float2*)(w3d + k * 64 + 2 * c) = make_float2(w, w);
    }
    if (tid < 128) { b1s[tid] = b1[tid]; b2s[tid] = b2[tid]; }

    // z0 = X(0) @ Wi + bi
    if (tid < 128) {
        const float* ca = coeffs + (size_t)r * 8192;
        float acc = bi[tid];
        #pragma unroll
        for (int c = 0; c < 32; c++)
            acc = fmaf(ca[c], Wi[c * 128 + tid], acc);
        zs[tid] = acc; ys[tid] = acc; kacc[tid] = 0.0f;
    }
    __syncthreads();

    const unsigned int base = *sbase;
    unsigned int bno = 0;

    // GEMM tiling: 4 rows x 2 cols per thread
    const int cg = tid & 15, rg = tid >> 4;
    const int r0 = rg << 2;             // batch rows r0..r0+3
    const int c0 = cg << 1;             // cols c0, c0+1
    unsigned int ha, wa;
    {
        u64 t = __cvta_generic_to_shared(h2s + r0);
        ha = (unsigned int)t;
        t = __cvta_generic_to_shared(w3d + (cg << 2));
        wa = (unsigned int)t;
    }
    const float2 b3v = *(const float2*)(b3 + r * 32 + c0);
    u64 Bc0, Bc1;
    asm("mov.b64 %0, {%1,%1};" : "=l"(Bc0) : "f"(b3v.x));
    asm("mov.b64 %0, {%1,%1};" : "=l"(Bc1) : "f"(b3v.y));

    for (int s = 0; s < 64; s++) {
        // publish dX for this segment (f=0, f=0.5, f=1)
        if (tid < 32) {
            const float* bc = coeffs + (size_t)r * 8192 + s * 128;
            int c = tid;
            float cb = bc[32 + c], c2 = bc[64 + c], c3 = bc[96 + c];
            g_dx[(r * 3 + 0) * 32 + c] = cb;
            g_dx[(r * 3 + 1) * 32 + c] = fmaf(0.25f, c3, fmaf(0.5f, c2, cb));
            g_dx[(r * 3 + 2) * 32 + c] = (s < 63) ? bc[128 + 32 + c]
                                                  : (cb + c2 + c3);
        }

        for (int stage = 0; stage < 4; stage++) {
            // ---- row-owner: layers 1,2 on own row, publish h2 ----
            gemv128(ys,  w1s, b1s, h1s,   sp);
            gemv128(h1s, w2s, b2s, h2row, sp);
            if (tid < 128)
                g_h2T[tid * 128 + r] = h2row[tid];

            grid_barrier(base + (++bno));   // A: all h2 rows + dX published

            // ---- stage h2T into smem ----
            #pragma unroll
            for (int i = 0; i < 8; i++)
                ((float4*)h2s)[tid + i * NT] = ((const float4*)g_h2T)[tid + i * NT];
            __syncthreads();

            // ---- GEMM: packed f32x2, zero dup movs ----
            u64 C0 = Bc0, C1 = Bc0;     // (r0,r1|c0), (r2,r3|c0)
            u64 C2 = Bc1, C3 = Bc1;     // (r0,r1|c1), (r2,r3|c1)
            {
                unsigned int hp = ha, wp = wa;
                #define MSTEP(KK)                                                     \
                {   u64 h01, h23, w01, w23;                                           \
                    asm("ld.shared.v2.b64 {%0,%1},[%2+%3];"                            \
                        : "=l"(h01), "=l"(h23) : "r"(hp), "n"((KK) * 512));            \
                    asm("ld.shared.v2.b64 {%0,%1},[%2+%3];"                            \
                        : "=l"(w01), "=l"(w23) : "r"(wp), "n"((KK) * 256));            \
                    asm("fma.rn.f32x2 %0,%1,%2,%0;" : "+l"(C0) : "l"(w01), "l"(h01));  \
                    asm("fma.rn.f32x2 %0,%1,%2,%0;" : "+l"(C1) : "l"(w01), "l"(h23));  \
                    asm("fma.rn.f32x2 %0,%1,%2,%0;" : "+l"(C2) : "l"(w23), "l"(h01));  \
                    asm("fma.rn.f32x2 %0,%1,%2,%0;" : "+l"(C3) : "l"(w23), "l"(h23)); }
                #pragma unroll 1
                for (int k8 = 0; k8 < 16; k8++) {
                    MSTEP(0) MSTEP(1) MSTEP(2) MSTEP(3)
                    MSTEP(4) MSTEP(5) MSTEP(6) MSTEP(7)
                    hp += 8 * 512; wp += 8 * 256;
                }
                #undef MSTEP
            }
            float x[8];   // [0..3]=col c0 rows 0..3, [4..7]=col c1 rows 0..3
            asm("mov.b64 {%0,%1}, %2;" : "=f"(x[0]), "=f"(x[1]) : "l"(C0));
            asm("mov.b64 {%0,%1}, %2;" : "=f"(x[2]), "=f"(x[3]) : "l"(C1));
            asm("mov.b64 {%0,%1}, %2;" : "=f"(x[4]), "=f"(x[5]) : "l"(C2));
            asm("mov.b64 {%0,%1}, %2;" : "=f"(x[6]), "=f"(x[7]) : "l"(C3));

            // ---- tanh + contraction with dX ----
            float p[8], q[8], inv[8];
            #pragma unroll
            for (int i = 0; i < 8; i++) p[i] = tanh_pq(x[i], q[i]);
            rcp4(q, inv); rcp4(q + 4, inv + 4);

            const int sel = (stage == 0) ? 0 : ((stage == 3) ? 2 : 1);
            float pr[4];
            #pragma unroll
            for (int i = 0; i < 4; i++) {
                float2 dd = *(const float2*)(g_dx + ((r0 + i) * 3 + sel) * 32 + c0);
                pr[i] = p[i] * inv[i] * dd.x + p[i + 4] * inv[i + 4] * dd.y;
            }
            #pragma unroll
            for (int off = 8; off >= 1; off >>= 1) {
                pr[0] += __shfl_down_sync(0xffffffffu, pr[0], off);
                pr[1] += __shfl_down_sync(0xffffffffu, pr[1], off);
                pr[2] += __shfl_down_sync(0xffffffffu, pr[2], off);
                pr[3] += __shfl_down_sync(0xffffffffu, pr[3], off);
            }
            if (cg == 0) {
                g_dz[(r0 + 0) * 128 + r] = pr[0];
                g_dz[(r0 + 1) * 128 + r] = pr[1];
                g_dz[(r0 + 2) * 128 + r] = pr[2];
                g_dz[(r0 + 3) * 128 + r] = pr[3];
            }

            grid_barrier(base + (++bno));   // B: dz complete

            // ---- row-owner: RK4 stage update ----
            if (tid < 32) {
                int h0 = tid << 2;
                float4 dz = *(const float4*)(g_dz + r * 128 + h0);
                float4 kq = *(float4*)(kacc + h0);
                float4 zq = *(float4*)(zs + h0);
                float kw = (stage == 0 || stage == 3) ? 1.0f : 2.0f;
                kq.x = fmaf(kw, dz.x, kq.x); kq.y = fmaf(kw, dz.y, kq.y);
                kq.z = fmaf(kw, dz.z, kq.z); kq.w = fmaf(kw, dz.w, kq.w);
                if (stage < 3) {
                    float aa = (stage == 2) ? 1.0f : 0.5f;
                    float4 yq;
                    yq.x = fmaf(aa, dz.x, zq.x); yq.y = fmaf(aa, dz.y, zq.y);
                    yq.z = fmaf(aa, dz.z, zq.z); yq.w = fmaf(aa, dz.w, zq.w);
                    *(float4*)(ys + h0) = yq;
                    *(float4*)(kacc + h0) = kq;
                } else {
                    const float c6 = 1.0f / 6.0f;
                    zq.x = fmaf(c6, kq.x, zq.x); zq.y = fmaf(c6, kq.y, zq.y);
                    zq.z = fmaf(c6, kq.z, zq.z); zq.w = fmaf(c6, kq.w, zq.w);
                    *(float4*)(zs + h0) = zq;
                    *(float4*)(ys + h0) = zq;
                    *(float4*)(kacc + h0) = make_float4(0.f, 0.f, 0.f, 0.f);
                }
            }
            __syncthreads();
        }
    }

    // ---- readout: out[r] = sigmoid(z @ Wr + br) ----
    if (tid < 32) {
        float part = 0.0f;
        #pragma unroll
        for (int h = tid; h < 128; h += 32)
            part = fmaf(zs[h], Wr[h], part);
        #pragma unroll
        for (int off = 16; off >= 1; off >>= 1)
            part += __shfl_down_sync(0xffffffffu, part, off);
        if (tid == 0)
            out[r] = 1.0f / (1.0f + __expf(-(part + br[0])));
    }
}

extern "C" void kernel_launch(void* const* d_in, const int* in_sizes, int n_in,
                              void* d_out, int out_size)
{
    const float* coeffs = (const float*)d_in[0];
    const float* W1 = (const float*)d_in[1];
    const float* b1 = (const float*)d_in[2];
    const float* W2 = (const float*)d_in[3];
    const float* b2 = (const float*)d_in[4];
    const float* W3 = (const float*)d_in[5];
    const float* b3 = (const float*)d_in[6];
    const float* Wi = (const float*)d_in[7];
    const float* bi = (const float*)d_in[8];
    const float* Wr = (const float*)d_in[9];
    const float* br = (const float*)d_in[10];
    float* out = (float*)d_out;

    cudaFuncSetAttribute(cde_kernel,
                         cudaFuncAttributeMaxDynamicSharedMemorySize, SMEM_BYTES);
    cde_kernel<<<NCTAS, NT, SMEM_BYTES>>>(coeffs, W1, b1, W2, b2, W3, b3,
                                          Wi, bi, Wr, br, out);
}